// round 14
// baseline (speedup 1.0000x reference)
#include <cuda_runtime.h>
#include <cuda_fp16.h>
#include <cstdint>

typedef unsigned long long ull;

// Shapes (fixed by the problem)
#define BB    64
#define NN    256
#define VD    2048
#define EMB   1024
#define MTOT  (BB*NN) // 16384

// gemm1 tiling
#define BM2   128
#define BK2   32
#define NS2   (VD/BK2)   // 64 stages
#define AST2  40         // halves per smem row (32 data + 8 pad)
#define ROWB  80         // bytes per smem row
#define ABUF  10240      // bytes per A buffer (128*80)
#define BSLOT 10240      // bytes per B slot
#define G1_SMEM (2*ABUF*2 + 4*BSLOT)   // 81920 bytes

// ---------------- scratch (no allocations allowed) ----------------
__device__ float g_scale[128];            // g/||v|| for U1 (0..63) and U2 (64..127)
__device__ float g_bias[128];             // b1 ‖ b2
__device__ __half g_Bh[128 * VD];         // weight rows, fp16 (U1 ‖ U2)
__device__ float g_LR[MTOT * 128];        // relu(V@Wcat^T + b): cols 0..63 right(U1), 64..127 left(U2)
__device__ float g_D[BB * NN];            // per-row rsqrt diag
__device__ float g_U4[BB * 4 * 64];       // 4-way partial u per batch
__device__ float g_feats4[4 * BB * VD];   // 4-way m-split partials of feats
__device__ float g_P[8 * BB * EMB];       // split-K partials for final GEMM

// ---------------- Kernel A: weight-norm prep + fp16 weight cast (merged) ----------------
__global__ __launch_bounds__(256) void k_prepB(const float* __restrict__ U1v, const float* __restrict__ U1g,
                                               const float* __restrict__ U1b, const float* __restrict__ U2v,
                                               const float* __restrict__ U2g, const float* __restrict__ U2b)
{
    __shared__ float red[8];
    const int w = blockIdx.x;            // 0..127
    const int t = threadIdx.x;
    const float* v = (w < 64) ? (U1v + (size_t)w * VD) : (U2v + (size_t)(w - 64) * VD);

    float x[8];
    float ss = 0.f;
    #pragma unroll
    for (int i = 0; i < 8; i++) { x[i] = v[t + i * 256]; ss = fmaf(x[i], x[i], ss); }
    #pragma unroll
    for (int o = 16; o > 0; o >>= 1) ss += __shfl_xor_sync(0xffffffffu, ss, o);
    if ((t & 31) == 0) red[t >> 5] = ss;
    __syncthreads();
    if (t == 0) {
        float tot = 0.f;
        #pragma unroll
        for (int i = 0; i < 8; i++) tot += red[i];
        float gg = (w < 64) ? U1g[w] : U2g[w - 64];
        float bb = (w < 64) ? U1b[w] : U2b[w - 64];
        g_scale[w] = gg / sqrtf(tot);
        g_bias[w]  = bb;
    }
    #pragma unroll
    for (int i = 0; i < 8; i++)
        g_Bh[w * VD + t + i * 256] = __float2half_rn(x[i]);
}

// ---------------- mma helpers ----------------
__device__ __forceinline__ void ldsm4(uint32_t* r, uint32_t a) {
    asm volatile("ldmatrix.sync.aligned.m8n8.x4.shared.b16 {%0,%1,%2,%3}, [%4];"
                 : "=r"(r[0]), "=r"(r[1]), "=r"(r[2]), "=r"(r[3]) : "r"(a));
}
__device__ __forceinline__ void mma16816(float* d, const uint32_t* a, const uint32_t* b) {
    asm volatile("mma.sync.aligned.m16n8k16.row.col.f32.f16.f16.f32 "
                 "{%0,%1,%2,%3},{%4,%5,%6,%7},{%8,%9},{%0,%1,%2,%3};"
                 : "+f"(d[0]), "+f"(d[1]), "+f"(d[2]), "+f"(d[3])
                 : "r"(a[0]), "r"(a[1]), "r"(a[2]), "r"(a[3]), "r"(b[0]), "r"(b[1]));
}
__device__ __forceinline__ void cp16(uint32_t dst, const void* src) {
    asm volatile("cp.async.ca.shared.global [%0], [%1], 16;" :: "r"(dst), "l"(src));
}
__device__ __forceinline__ unsigned h2bits(__half2 h) {
    return *reinterpret_cast<unsigned*>(&h);
}
// fp32 -> fp16 hi/lo split, packed pairs
__device__ __forceinline__ uint2 splitpackh(float4 av, uint2& lu) {
    __half2 h01 = __float22half2_rn(make_float2(av.x, av.y));
    __half2 h23 = __float22half2_rn(make_float2(av.z, av.w));
    float2 f01 = __half22float2(h01), f23 = __half22float2(h23);
    __half2 l01 = __float22half2_rn(make_float2(av.x - f01.x, av.y - f01.y));
    __half2 l23 = __float22half2_rn(make_float2(av.z - f23.x, av.w - f23.y));
    uint2 hu; hu.x = h2bits(h01); hu.y = h2bits(h23);
    lu.x = h2bits(l01); lu.y = h2bits(l23);
    return hu;
}

// ---------------- Kernel B: GEMM1 (fp16 2-product split, BM=128/BK=32) ----------------
// C[16384,128] = relu( (A[16384,2048] @ Wcat[128,2048]^T) * scale + bias )
// Grid 128 CTAs (one 128-row M tile each), 8 warps as 4(M)x2(N): warp tile M32xN64.
// Per stage per warp: 64 HMMA vs 16 ldsm (4:1); 64 stages (half the syncs of BK=16).
// A: fp32 LDG 2-stage reg lookahead -> fp16 hi/lo -> smem (2 bufs).
// B: fp16 via cp.async, 4-slot ring, issue s+3, wait_group 2.
__global__ __launch_bounds__(256) void k_gemm1(const float* __restrict__ A)
{
    extern __shared__ char dsm[];
    const uint32_t uB0 = (uint32_t)__cvta_generic_to_shared(dsm);
    const uint32_t uAh = uB0;                 // 2 x ABUF
    const uint32_t uAl = uB0 + 2 * ABUF;      // 2 x ABUF
    const uint32_t uBh = uB0 + 4 * ABUF;      // 4 x BSLOT
    __half* pAh = (__half*)dsm;
    __half* pAl = (__half*)(dsm + 2 * ABUF);

    const int t = threadIdx.x, lane = t & 31, warp = t >> 5;
    const int wy = warp >> 1;            // 0..3  (M quarter, 32 rows)
    const int wx = warp & 1;             // 0..1  (N half, 64 cols)
    const int blockRow = blockIdx.x * BM2;

    // ---- A loader role: row = t&127, half-of-32 = t>>7 (16 floats each) ----
    const int arow = t & 127, hs = t >> 7;
    const float* Ap = A + (size_t)(blockRow + arow) * VD + hs * 16;
    const uint32_t aSt = (uint32_t)(arow * ROWB + hs * 32);   // byte offset in buffer

    // ---- B loader role: row = t>>1, two 16B segs starting at (t&1)*2 ----
    const int brow = t >> 1, sg = (t & 1) * 2;
    const __half* Bp = g_Bh + (size_t)brow * VD + sg * 8;
    const uint32_t bDst = (uint32_t)(brow * ROWB + sg * 16);

    float acc[2][8][4];
    #pragma unroll
    for (int mi = 0; mi < 2; mi++)
        #pragma unroll
        for (int nt = 0; nt < 8; nt++)
            #pragma unroll
            for (int j = 0; j < 4; j++) acc[mi][nt][j] = 0.f;

    // ---- prologue: B slots 0..2 ----
    #pragma unroll
    for (int sl = 0; sl < 3; sl++) {
        cp16(uBh + sl * BSLOT + bDst,      Bp + sl * 32);
        cp16(uBh + sl * BSLOT + bDst + 16, Bp + sl * 32 + 8);
        asm volatile("cp.async.commit_group;");
    }
    // A stage 0 -> buf 0
    {
        #pragma unroll
        for (int j = 0; j < 4; j++) {
            float4 v = *(const float4*)(Ap + j * 4);
            uint2 lu, hu = splitpackh(v, lu);
            *(uint2*)((char*)pAh + aSt + j * 8) = hu;
            *(uint2*)((char*)pAl + aSt + j * 8) = lu;
        }
    }
    // A stage 1 into regs
    float4 a_cur[4];
    #pragma unroll
    for (int j = 0; j < 4; j++) a_cur[j] = *(const float4*)(Ap + BK2 + j * 4);

    asm volatile("cp.async.wait_group 2;");   // slot 0 ready
    __syncthreads();

    // per-warp ldmatrix byte offsets
    const uint32_t aLdBase = (uint32_t)((wy * 32 + (lane & 15)) * AST2 + ((lane >> 4) << 3)) * 2;
    const uint32_t bLdBase = (uint32_t)((wx * 64 + (lane & 7) + ((lane >> 4) << 3)) * AST2
                                        + (((lane >> 3) & 1) << 3)) * 2;
    const uint32_t mStep = (uint32_t)(16 * AST2 * 2);  // 16 rows in bytes (1280)

    for (int s = 0; s < NS2; ++s) {
        const int sl = s & 3, slp = (s + 3) & 3, ab = s & 1;
        if (s + 3 < NS2) {
            cp16(uBh + slp * BSLOT + bDst,      Bp + (s + 3) * 32);
            cp16(uBh + slp * BSLOT + bDst + 16, Bp + (s + 3) * 32 + 8);
        }
        asm volatile("cp.async.commit_group;");

        // A LDG for stage s+2
        float4 a_next[4];
        if (s + 2 < NS2) {
            #pragma unroll
            for (int j = 0; j < 4; j++)
                a_next[j] = *(const float4*)(Ap + (s + 2) * BK2 + j * 4);
        }
        // STS stage s+1 into buf (s+1)&1  (that buffer's readers synced last iter)
        if (s + 1 < NS2) {
            const uint32_t boff = (uint32_t)(((s + 1) & 1) * ABUF) + aSt;
            #pragma unroll
            for (int j = 0; j < 4; j++) {
                uint2 lu, hu = splitpackh(a_cur[j], lu);
                *(uint2*)((char*)pAh + boff + j * 8) = hu;
                *(uint2*)((char*)pAl + boff + j * 8) = lu;
            }
        }
        #pragma unroll
        for (int j = 0; j < 4; j++) a_cur[j] = a_next[j];

        // ---- compute stage s: 2 k-subtiles x (2 mi x 8 nt x 2 products) ----
        #pragma unroll
        for (int ks = 0; ks < 2; ks++) {
            const uint32_t kOff = (uint32_t)(ks * 32);   // 16 halves
            uint32_t ah[2][4], al[2][4], bh[4][4];
            #pragma unroll
            for (int mi = 0; mi < 2; mi++) {
                ldsm4(ah[mi], uAh + ab * ABUF + aLdBase + mi * mStep + kOff);
                ldsm4(al[mi], uAl + ab * ABUF + aLdBase + mi * mStep + kOff);
            }
            #pragma unroll
            for (int p = 0; p < 4; p++)
                ldsm4(bh[p], uBh + sl * BSLOT + bLdBase + p * mStep + kOff);
            #pragma unroll
            for (int mi = 0; mi < 2; mi++)
                #pragma unroll
                for (int nt = 0; nt < 8; nt++) {
                    mma16816(acc[mi][nt], ah[mi], &bh[nt >> 1][(nt & 1) * 2]);
                    mma16816(acc[mi][nt], al[mi], &bh[nt >> 1][(nt & 1) * 2]);
                }
        }

        asm volatile("cp.async.wait_group 2;");
        __syncthreads();
    }

    // ---- epilogue: scale + bias + relu -> g_LR ----
    #pragma unroll
    for (int mi = 0; mi < 2; mi++) {
        const int r0 = blockRow + wy * 32 + mi * 16 + (lane >> 2);
        #pragma unroll
        for (int nt = 0; nt < 8; nt++) {
            const int col = wx * 64 + nt * 8 + ((lane & 3) << 1);
            const float s0 = g_scale[col], s1 = g_scale[col + 1];
            const float b0 = g_bias[col],  b1 = g_bias[col + 1];
            float2 v;
            v.x = fmaxf(fmaf(acc[mi][nt][0], s0, b0), 0.f);
            v.y = fmaxf(fmaf(acc[mi][nt][1], s1, b1), 0.f);
            *(float2*)&g_LR[(size_t)r0 * 128 + col] = v;
            v.x = fmaxf(fmaf(acc[mi][nt][2], s0, b0), 0.f);
            v.y = fmaxf(fmaf(acc[mi][nt][3], s1, b1), 0.f);
            *(float2*)&g_LR[(size_t)(r0 + 8) * 128 + col] = v;
        }
    }
}

// ---------------- Kernel C1: per-row d + 4-way partial u ----------------
// grid (4, BB), 256 threads; 4 lanes per row.
__global__ __launch_bounds__(256) void k_corrA()
{
    __shared__ float d_s[64];
    __shared__ float upart[4][64];
    const int b = blockIdx.y, q = blockIdx.x, t = threadIdx.x;
    const int row = t >> 2, c = t & 3;
    const int gr = b * NN + q * 64 + row;
    const float* myrow = g_LR + (size_t)gr * 128;

    float dot = 0.f;
    #pragma unroll
    for (int j = 0; j < 4; j++) {
        float4 r = ((const float4*)myrow)[c + j * 4];
        float4 l = ((const float4*)myrow)[16 + c + j * 4];
        dot += r.x * l.x + r.y * l.y + r.z * l.z + r.w * l.w;
    }
    dot += __shfl_xor_sync(0xffffffffu, dot, 1);
    dot += __shfl_xor_sync(0xffffffffu, dot, 2);
    const float dv = rsqrtf(dot + 1e-6f);
    if (c == 0) { d_s[row] = dv; g_D[gr] = dv; }
    __syncthreads();

    const int k = t & 63, g = t >> 6;
    float part = 0.f;
    const float* lb = g_LR + (size_t)(b * NN + q * 64 + g * 16) * 128 + 64 + k;
    #pragma unroll
    for (int n = 0; n < 16; n++)
        part = fmaf(d_s[g * 16 + n], lb[(size_t)n * 128], part);
    upart[g][k] = part;
    __syncthreads();
    if (t < 64)
        g_U4[(b * 4 + q) * 64 + t] = upart[0][t] + upart[1][t] + upart[2][t] + upart[3][t];
}

// ---------------- Kernel D: s[m] (fused corrB) + feats partials ----------------
// grid (2, 4, BB): x = v-half, y = m-quarter q, z = batch.
__global__ __launch_bounds__(256) void k_featsS(const float* __restrict__ V)
{
    __shared__ float u_s[64];
    __shared__ float ss[64];
    const int b = blockIdx.z, q = blockIdx.y;
    const int t = threadIdx.x;

    if (t < 64)
        u_s[t] = g_U4[(b * 4 + 0) * 64 + t] + g_U4[(b * 4 + 1) * 64 + t]
               + g_U4[(b * 4 + 2) * 64 + t] + g_U4[(b * 4 + 3) * 64 + t];
    __syncthreads();

    {   // s for this block's 64 rows (4 lanes per row)
        const int row = t >> 2, c = t & 3;
        const int gr = b * NN + q * 64 + row;
        const float* myrow = g_LR + (size_t)gr * 128;
        float sm = 0.f;
        #pragma unroll
        for (int j = 0; j < 4; j++) {
            float4 r = ((const float4*)myrow)[c * 4 + j];
            sm += u_s[c * 16 + j * 4 + 0] * r.x + u_s[c * 16 + j * 4 + 1] * r.y
                + u_s[c * 16 + j * 4 + 2] * r.z + u_s[c * 16 + j * 4 + 3] * r.w;
        }
        sm += __shfl_xor_sync(0xffffffffu, sm, 1);
        sm += __shfl_xor_sync(0xffffffffu, sm, 2);
        if (c == 0)
            ss[row] = 1.f + (1.f / 256.f) - (g_D[gr] * (1.f / 256.f)) * sm;
    }
    __syncthreads();

    const int v0 = (blockIdx.x * 256 + t) * 4;
    const float* base = V + (size_t)b * NN * VD + (size_t)q * 64 * VD + v0;
    float4 acc = make_float4(0.f, 0.f, 0.f, 0.f);
    #pragma unroll 4
    for (int m = 0; m < 64; m++) {
        float4 val = *(const float4*)(base + (size_t)m * VD);
        float sv = ss[m];
        acc.x = fmaf(sv, val.x, acc.x);
        acc.y = fmaf(sv, val.y, acc.y);
        acc.z = fmaf(sv, val.z, acc.z);
        acc.w = fmaf(sv, val.w, acc.w);
    }
    *(float4*)(g_feats4 + (size_t)(q * BB + b) * VD + v0) = acc;
}

// ---------------- Kernel E: split-K GEMM  x = feats @ W^T  ->  partials g_P ----------------
__global__ __launch_bounds__(256) void k_gemm2(const float* __restrict__ W)
{
    __shared__ float sA[32][65];
    __shared__ float sB[32][65];
    const int t = threadIdx.x;
    const int tx = t & 15, ty = t >> 4;
    const int e0 = blockIdx.x * 64;
    const int k0 = blockIdx.y * 256;
    const int lrow = t >> 2, lk = (t & 3) * 8;
    float acc[4][4] = {};

    for (int stage = 0; stage < 8; ++stage) {
        const int kb = k0 + stage * 32;
        float4 a0 = make_float4(0,0,0,0), a1 = make_float4(0,0,0,0);
        #pragma unroll
        for (int p = 0; p < 4; p++) {
            float4 t0 = *(const float4*)(g_feats4 + (size_t)(p * BB + lrow) * VD + kb + lk);
            float4 t1 = *(const float4*)(g_feats4 + (size_t)(p * BB + lrow) * VD + kb + lk + 4);
            a0.x += t0.x; a0.y += t0.y; a0.z += t0.z; a0.w += t0.w;
            a1.x += t1.x; a1.y += t1.y; a1.z += t1.z; a1.w += t1.w;
        }
        float4 w0 = *(const float4*)(W + (size_t)(e0 + lrow) * VD + kb + lk);
        float4 w1 = *(const float4*)(W + (size_t)(e0 + lrow) * VD + kb + lk + 4);
        __syncthreads();
        sA[lk+0][lrow]=a0.x; sA[lk+1][lrow]=a0.y; sA[lk+2][lrow]=a0.z; sA[lk+3][lrow]=a0.w;
        sA[lk+4][lrow]=a1.x; sA[lk+5][lrow]=a1.y; sA[lk+6][lrow]=a1.z; sA[lk+7][lrow]=a1.w;
        sB[lk+0][lrow]=w0.x; sB[lk+1][lrow]=w0.y; sB[lk+2][lrow]=w0.z; sB[lk+3][lrow]=w0.w;
        sB[lk+4][lrow]=w1.x; sB[lk+5][lrow]=w1.y; sB[lk+6][lrow]=w1.z; sB[lk+7][lrow]=w1.w;
        __syncthreads();
        #pragma unroll
        for (int k = 0; k < 32; k++) {
            float av[4], bv[4];
            #pragma unroll
            for (int i = 0; i < 4; i++) av[i] = sA[k][ty * 4 + i];
            #pragma unroll
            for (int j = 0; j < 4; j++) bv[j] = sB[k][tx * 4 + j];
            #pragma unroll
            for (int i = 0; i < 4; i++)
                #pragma unroll
                for (int j = 0; j < 4; j++) acc[i][j] = fmaf(av[i], bv[j], acc[i][j]);
        }
    }
    #pragma unroll
    for (int i = 0; i < 4; i++)
        #pragma unroll
        for (int j = 0; j < 4; j++)
            g_P[(size_t)(blockIdx.y * 64 + ty * 4 + i) * EMB + e0 + tx * 4 + j] = acc[i][j];
}

// ---------------- Kernel F: reduce split-K + BatchNorm (single memory pass) ----------------
__global__ __launch_bounds__(256) void k_bn(const float* __restrict__ b_lin,
                                            const float* __restrict__ gamma,
                                            const float* __restrict__ beta,
                                            float* __restrict__ out)
{
    const int e = blockIdx.x * 256 + threadIdx.x;
    const float bias = b_lin[e];
    float x[BB];
    float sum = 0.f;
    #pragma unroll
    for (int b = 0; b < BB; b++) {
        float v = bias;
        #pragma unroll
        for (int s = 0; s < 8; s++) v += g_P[(size_t)(s * BB + b) * EMB + e];
        x[b] = v; sum += v;
    }
    const float mu = sum * (1.f / BB);
    float sq = 0.f;
    #pragma unroll
    for (int b = 0; b < BB; b++) { float d = x[b] - mu; sq = fmaf(d, d, sq); }
    const float inv = rsqrtf(sq * (1.f / BB) + 1e-5f);
    const float ga = gamma[e] * inv, be = beta[e];
    #pragma unroll
    for (int b = 0; b < BB; b++)
        out[b * EMB + e] = fmaf(ga, x[b] - mu, be);
}

// ---------------- launch ----------------
extern "C" void kernel_launch(void* const* d_in, const int* in_sizes, int n_in,
                              void* d_out, int out_size)
{
    const float* Vmat = (const float*)d_in[0];
    const float* U1v  = (const float*)d_in[1];
    const float* U1g  = (const float*)d_in[2];
    const float* U1b  = (const float*)d_in[3];
    const float* U2v  = (const float*)d_in[4];
    const float* U2g  = (const float*)d_in[5];
    const float* U2b  = (const float*)d_in[6];
    const float* Wl   = (const float*)d_in[7];
    const float* bl   = (const float*)d_in[8];
    const float* gam  = (const float*)d_in[9];
    const float* bet  = (const float*)d_in[10];
    float* out = (float*)d_out;

    cudaFuncSetAttribute(k_gemm1, cudaFuncAttributeMaxDynamicSharedMemorySize, G1_SMEM);

    k_prepB<<<128, 256>>>(U1v, U1g, U1b, U2v, U2g, U2b);
    k_gemm1<<<MTOT / BM2, 256, G1_SMEM>>>(Vmat);
    k_corrA<<<dim3(4, BB), 256>>>();
    k_featsS<<<dim3(2, 4, BB), 256>>>(Vmat);
    k_gemm2<<<dim3(EMB / 64, 8), 256>>>(Wl);
    k_bn<<<EMB / 256, 256>>>(bl, gam, bet, out);
}

// round 15
// speedup vs baseline: 1.3271x; 1.3271x over previous
#include <cuda_runtime.h>
#include <cuda_fp16.h>
#include <cstdint>

typedef unsigned long long ull;

// Shapes (fixed by the problem)
#define BB    64
#define NN    256
#define VD    2048
#define EMB   1024
#define MTOT  (BB*NN) // 16384

// gemm1 tiling: BM=64, BK=32, 2 CTAs/SM (R12 geometry, wider K stage)
#define BK2   32
#define NS2   (VD/BK2)    // 64 stages
#define AST2  40          // halves per smem row (32 data + 8 pad)
#define ROWB  80          // bytes per smem row
#define ABUFA 5120        // bytes per A buffer (64*80)
#define BSLOT 10240       // bytes per B slot (128*80)
#define G1_SMEM (2*ABUFA*2 + 4*BSLOT)   // 61440 bytes/CTA -> 2 CTAs = 120 KB/SM

// ---------------- scratch (no allocations allowed) ----------------
__device__ float g_scale[128];            // g/||v|| for U1 (0..63) and U2 (64..127)
__device__ float g_bias[128];             // b1 ‖ b2
__device__ __half g_Bh[128 * VD];         // weight rows, fp16 (U1 ‖ U2)
__device__ float g_LR[MTOT * 128];        // relu(V@Wcat^T + b): cols 0..63 right(U1), 64..127 left(U2)
__device__ float g_D[BB * NN];            // per-row rsqrt diag
__device__ float g_U4[BB * 4 * 64];       // 4-way partial u per batch
__device__ float g_feats4[4 * BB * VD];   // 4-way m-split partials of feats
__device__ float g_P[8 * BB * EMB];       // split-K partials for final GEMM

// ---------------- Kernel A: weight-norm prep + fp16 weight cast (merged) ----------------
__global__ __launch_bounds__(256) void k_prepB(const float* __restrict__ U1v, const float* __restrict__ U1g,
                                               const float* __restrict__ U1b, const float* __restrict__ U2v,
                                               const float* __restrict__ U2g, const float* __restrict__ U2b)
{
    __shared__ float red[8];
    const int w = blockIdx.x;            // 0..127
    const int t = threadIdx.x;
    const float* v = (w < 64) ? (U1v + (size_t)w * VD) : (U2v + (size_t)(w - 64) * VD);

    float x[8];
    float ss = 0.f;
    #pragma unroll
    for (int i = 0; i < 8; i++) { x[i] = v[t + i * 256]; ss = fmaf(x[i], x[i], ss); }
    #pragma unroll
    for (int o = 16; o > 0; o >>= 1) ss += __shfl_xor_sync(0xffffffffu, ss, o);
    if ((t & 31) == 0) red[t >> 5] = ss;
    __syncthreads();
    if (t == 0) {
        float tot = 0.f;
        #pragma unroll
        for (int i = 0; i < 8; i++) tot += red[i];
        float gg = (w < 64) ? U1g[w] : U2g[w - 64];
        float bb = (w < 64) ? U1b[w] : U2b[w - 64];
        g_scale[w] = gg / sqrtf(tot);
        g_bias[w]  = bb;
    }
    #pragma unroll
    for (int i = 0; i < 8; i++)
        g_Bh[w * VD + t + i * 256] = __float2half_rn(x[i]);
}

// ---------------- mma helpers ----------------
__device__ __forceinline__ void ldsm4(uint32_t* r, uint32_t a) {
    asm volatile("ldmatrix.sync.aligned.m8n8.x4.shared.b16 {%0,%1,%2,%3}, [%4];"
                 : "=r"(r[0]), "=r"(r[1]), "=r"(r[2]), "=r"(r[3]) : "r"(a));
}
__device__ __forceinline__ void mma16816(float* d, const uint32_t* a, const uint32_t* b) {
    asm volatile("mma.sync.aligned.m16n8k16.row.col.f32.f16.f16.f32 "
                 "{%0,%1,%2,%3},{%4,%5,%6,%7},{%8,%9},{%0,%1,%2,%3};"
                 : "+f"(d[0]), "+f"(d[1]), "+f"(d[2]), "+f"(d[3])
                 : "r"(a[0]), "r"(a[1]), "r"(a[2]), "r"(a[3]), "r"(b[0]), "r"(b[1]));
}
__device__ __forceinline__ void cp16(uint32_t dst, const void* src) {
    asm volatile("cp.async.ca.shared.global [%0], [%1], 16;" :: "r"(dst), "l"(src));
}
__device__ __forceinline__ unsigned h2bits(__half2 h) {
    return *reinterpret_cast<unsigned*>(&h);
}
// fp32 -> fp16 hi/lo split, packed pairs
__device__ __forceinline__ uint2 splitpackh(float4 av, uint2& lu) {
    __half2 h01 = __float22half2_rn(make_float2(av.x, av.y));
    __half2 h23 = __float22half2_rn(make_float2(av.z, av.w));
    float2 f01 = __half22float2(h01), f23 = __half22float2(h23);
    __half2 l01 = __float22half2_rn(make_float2(av.x - f01.x, av.y - f01.y));
    __half2 l23 = __float22half2_rn(make_float2(av.z - f23.x, av.w - f23.y));
    uint2 hu; hu.x = h2bits(h01); hu.y = h2bits(h23);
    lu.x = h2bits(l01); lu.y = h2bits(l23);
    return hu;
}

// ---------------- Kernel B: GEMM1 (fp16 2-product split, BM=64/BK=32, 2 CTAs/SM) ----------------
// C[16384,128] = relu( (A[16384,2048] @ Wcat[128,2048]^T) * scale + bias )
// 256 CTAs, 8 warps as 2(M)x4(N): warp tile M32xN32. 64 stages.
// Per stage per warp: 32 HMMA vs 12 ldsm + 1 sync (R12 had 16 vs 6 + 1 at 128 stages).
// A: fp32 LDG 2-stage reg lookahead -> fp16 hi/lo -> smem (2 bufs).
// B: fp16 via cp.async, 4-slot ring, issue s+3, wait_group 2.
__global__ __launch_bounds__(256, 2) void k_gemm1(const float* __restrict__ A)
{
    extern __shared__ char dsm[];
    const uint32_t uB0 = (uint32_t)__cvta_generic_to_shared(dsm);
    const uint32_t uAh = uB0;                  // 2 x ABUFA
    const uint32_t uAl = uB0 + 2 * ABUFA;      // 2 x ABUFA
    const uint32_t uBh = uB0 + 4 * ABUFA;      // 4 x BSLOT
    char* pAh = dsm;
    char* pAl = dsm + 2 * ABUFA;

    const int t = threadIdx.x, lane = t & 31, warp = t >> 5;
    const int wy = warp >> 2;           // 0..1  (M half, 32 rows)
    const int wx = warp & 3;            // 0..3  (N quarter, 32 cols)
    const int blockRow = blockIdx.x * 64;

    // ---- A loader role: row = t>>2 (0..63), 8 floats at (t&3)*8 ----
    const int arow = t >> 2, ak = (t & 3) * 8;
    const float* Ap = A + (size_t)(blockRow + arow) * VD + ak;
    const uint32_t aSt = (uint32_t)(arow * ROWB + ak * 2);    // byte offset in buffer

    // ---- B loader role: row = t>>1 (0..127), 32B seg at (t&1)*32 ----
    const int brow = t >> 1, sg = t & 1;
    const __half* Bp = g_Bh + (size_t)brow * VD + sg * 16;    // 16 halves = 32B
    const uint32_t bDst = (uint32_t)(brow * ROWB + sg * 32);

    float acc[2][4][4];
    #pragma unroll
    for (int mi = 0; mi < 2; mi++)
        #pragma unroll
        for (int nt = 0; nt < 4; nt++)
            #pragma unroll
            for (int j = 0; j < 4; j++) acc[mi][nt][j] = 0.f;

    // ---- prologue: B slots 0..2 ----
    #pragma unroll
    for (int sl = 0; sl < 3; sl++) {
        cp16(uBh + sl * BSLOT + bDst,      Bp + sl * BK2);
        cp16(uBh + sl * BSLOT + bDst + 16, Bp + sl * BK2 + 8);
        asm volatile("cp.async.commit_group;");
    }
    // A stage 0 -> buf 0
    {
        #pragma unroll
        for (int j = 0; j < 2; j++) {
            float4 v = *(const float4*)(Ap + j * 4);
            uint2 lu, hu = splitpackh(v, lu);
            *(uint2*)(pAh + aSt + j * 8) = hu;
            *(uint2*)(pAl + aSt + j * 8) = lu;
        }
    }
    // A stage 1 into regs
    float4 a_cur[2];
    #pragma unroll
    for (int j = 0; j < 2; j++) a_cur[j] = *(const float4*)(Ap + BK2 + j * 4);

    asm volatile("cp.async.wait_group 2;");   // slot 0 ready
    __syncthreads();

    // per-warp ldmatrix byte offsets
    const uint32_t aLdBase = (uint32_t)((wy * 32 + (lane & 15)) * AST2 + ((lane >> 4) << 3)) * 2;
    const uint32_t bLdBase = (uint32_t)((wx * 32 + (lane & 7) + ((lane >> 4) << 3)) * AST2
                                        + (((lane >> 3) & 1) << 3)) * 2;
    const uint32_t mStep = (uint32_t)(16 * AST2 * 2);  // 16 rows in bytes (1280)

    for (int s = 0; s < NS2; ++s) {
        const int sl = s & 3, slp = (s + 3) & 3, ab = s & 1;
        if (s + 3 < NS2) {
            cp16(uBh + slp * BSLOT + bDst,      Bp + (s + 3) * BK2);
            cp16(uBh + slp * BSLOT + bDst + 16, Bp + (s + 3) * BK2 + 8);
        }
        asm volatile("cp.async.commit_group;");

        // A LDG for stage s+2
        float4 a_next[2];
        if (s + 2 < NS2) {
            #pragma unroll
            for (int j = 0; j < 2; j++)
                a_next[j] = *(const float4*)(Ap + (s + 2) * BK2 + j * 4);
        }
        // STS stage s+1 into buf (s+1)&1  (that buffer's readers synced last iter)
        if (s + 1 < NS2) {
            const uint32_t boff = (uint32_t)(((s + 1) & 1) * ABUFA) + aSt;
            #pragma unroll
            for (int j = 0; j < 2; j++) {
                uint2 lu, hu = splitpackh(a_cur[j], lu);
                *(uint2*)(pAh + boff + j * 8) = hu;
                *(uint2*)(pAl + boff + j * 8) = lu;
            }
        }
        #pragma unroll
        for (int j = 0; j < 2; j++) a_cur[j] = a_next[j];

        // ---- compute stage s: 2 k-subtiles x (2 mi x 4 nt x 2 products) ----
        #pragma unroll
        for (int ks = 0; ks < 2; ks++) {
            const uint32_t kOff = (uint32_t)(ks * 32);   // 16 halves = 32B
            uint32_t ah[2][4], al[2][4], bh[2][4];
            #pragma unroll
            for (int mi = 0; mi < 2; mi++) {
                ldsm4(ah[mi], uAh + ab * ABUFA + aLdBase + mi * mStep + kOff);
                ldsm4(al[mi], uAl + ab * ABUFA + aLdBase + mi * mStep + kOff);
            }
            #pragma unroll
            for (int nj = 0; nj < 2; nj++)
                ldsm4(bh[nj], uBh + sl * BSLOT + bLdBase + nj * mStep + kOff);
            #pragma unroll
            for (int mi = 0; mi < 2; mi++)
                #pragma unroll
                for (int nt = 0; nt < 4; nt++) {
                    mma16816(acc[mi][nt], ah[mi], &bh[nt >> 1][(nt & 1) * 2]);
                    mma16816(acc[mi][nt], al[mi], &bh[nt >> 1][(nt & 1) * 2]);
                }
        }

        asm volatile("cp.async.wait_group 2;");
        __syncthreads();
    }

    // ---- epilogue: scale + bias + relu -> g_LR ----
    #pragma unroll
    for (int mi = 0; mi < 2; mi++) {
        const int r0 = blockRow + wy * 32 + mi * 16 + (lane >> 2);
        #pragma unroll
        for (int nt = 0; nt < 4; nt++) {
            const int col = wx * 32 + nt * 8 + ((lane & 3) << 1);
            const float s0 = g_scale[col], s1 = g_scale[col + 1];
            const float b0 = g_bias[col],  b1 = g_bias[col + 1];
            float2 v;
            v.x = fmaxf(fmaf(acc[mi][nt][0], s0, b0), 0.f);
            v.y = fmaxf(fmaf(acc[mi][nt][1], s1, b1), 0.f);
            *(float2*)&g_LR[(size_t)r0 * 128 + col] = v;
            v.x = fmaxf(fmaf(acc[mi][nt][2], s0, b0), 0.f);
            v.y = fmaxf(fmaf(acc[mi][nt][3], s1, b1), 0.f);
            *(float2*)&g_LR[(size_t)(r0 + 8) * 128 + col] = v;
        }
    }
}

// ---------------- Kernel C1: per-row d + 4-way partial u ----------------
// grid (4, BB), 256 threads; 4 lanes per row.
__global__ __launch_bounds__(256) void k_corrA()
{
    __shared__ float d_s[64];
    __shared__ float upart[4][64];
    const int b = blockIdx.y, q = blockIdx.x, t = threadIdx.x;
    const int row = t >> 2, c = t & 3;
    const int gr = b * NN + q * 64 + row;
    const float* myrow = g_LR + (size_t)gr * 128;

    float dot = 0.f;
    #pragma unroll
    for (int j = 0; j < 4; j++) {
        float4 r = ((const float4*)myrow)[c + j * 4];
        float4 l = ((const float4*)myrow)[16 + c + j * 4];
        dot += r.x * l.x + r.y * l.y + r.z * l.z + r.w * l.w;
    }
    dot += __shfl_xor_sync(0xffffffffu, dot, 1);
    dot += __shfl_xor_sync(0xffffffffu, dot, 2);
    const float dv = rsqrtf(dot + 1e-6f);
    if (c == 0) { d_s[row] = dv; g_D[gr] = dv; }
    __syncthreads();

    const int k = t & 63, g = t >> 6;
    float part = 0.f;
    const float* lb = g_LR + (size_t)(b * NN + q * 64 + g * 16) * 128 + 64 + k;
    #pragma unroll
    for (int n = 0; n < 16; n++)
        part = fmaf(d_s[g * 16 + n], lb[(size_t)n * 128], part);
    upart[g][k] = part;
    __syncthreads();
    if (t < 64)
        g_U4[(b * 4 + q) * 64 + t] = upart[0][t] + upart[1][t] + upart[2][t] + upart[3][t];
}

// ---------------- Kernel D: s[m] (fused corrB) + feats partials ----------------
// grid (2, 4, BB): x = v-half, y = m-quarter q, z = batch.
__global__ __launch_bounds__(256) void k_featsS(const float* __restrict__ V)
{
    __shared__ float u_s[64];
    __shared__ float ss[64];
    const int b = blockIdx.z, q = blockIdx.y;
    const int t = threadIdx.x;

    if (t < 64)
        u_s[t] = g_U4[(b * 4 + 0) * 64 + t] + g_U4[(b * 4 + 1) * 64 + t]
               + g_U4[(b * 4 + 2) * 64 + t] + g_U4[(b * 4 + 3) * 64 + t];
    __syncthreads();

    {   // s for this block's 64 rows (4 lanes per row)
        const int row = t >> 2, c = t & 3;
        const int gr = b * NN + q * 64 + row;
        const float* myrow = g_LR + (size_t)gr * 128;
        float sm = 0.f;
        #pragma unroll
        for (int j = 0; j < 4; j++) {
            float4 r = ((const float4*)myrow)[c * 4 + j];
            sm += u_s[c * 16 + j * 4 + 0] * r.x + u_s[c * 16 + j * 4 + 1] * r.y
                + u_s[c * 16 + j * 4 + 2] * r.z + u_s[c * 16 + j * 4 + 3] * r.w;
        }
        sm += __shfl_xor_sync(0xffffffffu, sm, 1);
        sm += __shfl_xor_sync(0xffffffffu, sm, 2);
        if (c == 0)
            ss[row] = 1.f + (1.f / 256.f) - (g_D[gr] * (1.f / 256.f)) * sm;
    }
    __syncthreads();

    const int v0 = (blockIdx.x * 256 + t) * 4;
    const float* base = V + (size_t)b * NN * VD + (size_t)q * 64 * VD + v0;
    float4 acc = make_float4(0.f, 0.f, 0.f, 0.f);
    #pragma unroll 4
    for (int m = 0; m < 64; m++) {
        float4 val = *(const float4*)(base + (size_t)m * VD);
        float sv = ss[m];
        acc.x = fmaf(sv, val.x, acc.x);
        acc.y = fmaf(sv, val.y, acc.y);
        acc.z = fmaf(sv, val.z, acc.z);
        acc.w = fmaf(sv, val.w, acc.w);
    }
    *(float4*)(g_feats4 + (size_t)(q * BB + b) * VD + v0) = acc;
}

// ---------------- Kernel E: split-K GEMM  x = feats @ W^T  ->  partials g_P ----------------
__global__ __launch_bounds__(256) void k_gemm2(const float* __restrict__ W)
{
    __shared__ float sA[32][65];
    __shared__ float sB[32][65];
    const int t = threadIdx.x;
    const int tx = t & 15, ty = t >> 4;
    const int e0 = blockIdx.x * 64;
    const int k0 = blockIdx.y * 256;
    const int lrow = t >> 2, lk = (t & 3) * 8;
    float acc[4][4] = {};

    for (int stage = 0; stage < 8; ++stage) {
        const int kb = k0 + stage * 32;
        float4 a0 = make_float4(0,0,0,0), a1 = make_float4(0,0,0,0);
        #pragma unroll
        for (int p = 0; p < 4; p++) {
            float4 t0 = *(const float4*)(g_feats4 + (size_t)(p * BB + lrow) * VD + kb + lk);
            float4 t1 = *(const float4*)(g_feats4 + (size_t)(p * BB + lrow) * VD + kb + lk + 4);
            a0.x += t0.x; a0.y += t0.y; a0.z += t0.z; a0.w += t0.w;
            a1.x += t1.x; a1.y += t1.y; a1.z += t1.z; a1.w += t1.w;
        }
        float4 w0 = *(const float4*)(W + (size_t)(e0 + lrow) * VD + kb + lk);
        float4 w1 = *(const float4*)(W + (size_t)(e0 + lrow) * VD + kb + lk + 4);
        __syncthreads();
        sA[lk+0][lrow]=a0.x; sA[lk+1][lrow]=a0.y; sA[lk+2][lrow]=a0.z; sA[lk+3][lrow]=a0.w;
        sA[lk+4][lrow]=a1.x; sA[lk+5][lrow]=a1.y; sA[lk+6][lrow]=a1.z; sA[lk+7][lrow]=a1.w;
        sB[lk+0][lrow]=w0.x; sB[lk+1][lrow]=w0.y; sB[lk+2][lrow]=w0.z; sB[lk+3][lrow]=w0.w;
        sB[lk+4][lrow]=w1.x; sB[lk+5][lrow]=w1.y; sB[lk+6][lrow]=w1.z; sB[lk+7][lrow]=w1.w;
        __syncthreads();
        #pragma unroll
        for (int k = 0; k < 32; k++) {
            float av[4], bv[4];
            #pragma unroll
            for (int i = 0; i < 4; i++) av[i] = sA[k][ty * 4 + i];
            #pragma unroll
            for (int j = 0; j < 4; j++) bv[j] = sB[k][tx * 4 + j];
            #pragma unroll
            for (int i = 0; i < 4; i++)
                #pragma unroll
                for (int j = 0; j < 4; j++) acc[i][j] = fmaf(av[i], bv[j], acc[i][j]);
        }
    }
    #pragma unroll
    for (int i = 0; i < 4; i++)
        #pragma unroll
        for (int j = 0; j < 4; j++)
            g_P[(size_t)(blockIdx.y * 64 + ty * 4 + i) * EMB + e0 + tx * 4 + j] = acc[i][j];
}

// ---------------- Kernel F: reduce split-K + BatchNorm (single memory pass) ----------------
__global__ __launch_bounds__(256) void k_bn(const float* __restrict__ b_lin,
                                            const float* __restrict__ gamma,
                                            const float* __restrict__ beta,
                                            float* __restrict__ out)
{
    const int e = blockIdx.x * 256 + threadIdx.x;
    const float bias = b_lin[e];
    float x[BB];
    float sum = 0.f;
    #pragma unroll
    for (int b = 0; b < BB; b++) {
        float v = bias;
        #pragma unroll
        for (int s = 0; s < 8; s++) v += g_P[(size_t)(s * BB + b) * EMB + e];
        x[b] = v; sum += v;
    }
    const float mu = sum * (1.f / BB);
    float sq = 0.f;
    #pragma unroll
    for (int b = 0; b < BB; b++) { float d = x[b] - mu; sq = fmaf(d, d, sq); }
    const float inv = rsqrtf(sq * (1.f / BB) + 1e-5f);
    const float ga = gamma[e] * inv, be = beta[e];
    #pragma unroll
    for (int b = 0; b < BB; b++)
        out[b * EMB + e] = fmaf(ga, x[b] - mu, be);
}

// ---------------- launch ----------------
extern "C" void kernel_launch(void* const* d_in, const int* in_sizes, int n_in,
                              void* d_out, int out_size)
{
    const float* Vmat = (const float*)d_in[0];
    const float* U1v  = (const float*)d_in[1];
    const float* U1g  = (const float*)d_in[2];
    const float* U1b  = (const float*)d_in[3];
    const float* U2v  = (const float*)d_in[4];
    const float* U2g  = (const float*)d_in[5];
    const float* U2b  = (const float*)d_in[6];
    const float* Wl   = (const float*)d_in[7];
    const float* bl   = (const float*)d_in[8];
    const float* gam  = (const float*)d_in[9];
    const float* bet  = (const float*)d_in[10];
    float* out = (float*)d_out;

    cudaFuncSetAttribute(k_gemm1, cudaFuncAttributeMaxDynamicSharedMemorySize, G1_SMEM);

    k_prepB<<<128, 256>>>(U1v, U1g, U1b, U2v, U2g, U2b);
    k_gemm1<<<MTOT / 64, 256, G1_SMEM>>>(Vmat);
    k_corrA<<<dim3(4, BB), 256>>>();
    k_featsS<<<dim3(2, 4, BB), 256>>>(Vmat);
    k_gemm2<<<dim3(EMB / 64, 8), 256>>>(Wl);
    k_bn<<<EMB / 256, 256>>>(bl, gam, bet, out);
}

// round 17
// speedup vs baseline: 1.5255x; 1.1495x over previous
#include <cuda_runtime.h>
#include <cuda_fp16.h>
#include <cstdint>

typedef unsigned long long ull;

// Shapes (fixed by the problem)
#define BB    64
#define NN    256
#define VD    2048
#define EMB   1024
#define MTOT  (BB*NN) // 16384

// gemm1 tiling: BM=64, BK=32, single fp16 product
#define BK2   32
#define NS2   (VD/BK2)    // 64 stages
#define AST2  40          // halves per smem row (32 data + 8 pad)
#define ROWB  80          // bytes per smem row
#define ABUFA 5120        // bytes per A buffer (64*80)
#define BSLOT 10240       // bytes per B slot (128*80)
#define G1_SMEM (2*ABUFA + 4*BSLOT)   // 51200 bytes/CTA

// ---------------- scratch (no allocations allowed) ----------------
__device__ float g_scale[128];            // g/||v|| for U1 (0..63) and U2 (64..127)
__device__ float g_bias[128];             // b1 ‖ b2
__device__ __half g_Bh[128 * VD];         // weight rows, fp16 (U1 ‖ U2)
__device__ float g_LR[MTOT * 128];        // relu(V@Wcat^T + b): cols 0..63 right(U1), 64..127 left(U2)
__device__ float g_D[BB * NN];            // per-row rsqrt diag
__device__ float g_U4[BB * 4 * 64];       // 4-way partial u per batch
__device__ float g_feats4[4 * BB * VD];   // 4-way m-split partials of feats
__device__ float g_P[8 * BB * EMB];       // split-K partials for final GEMM

// ---------------- Kernel A: weight-norm prep + fp16 weight cast (merged) ----------------
__global__ __launch_bounds__(256) void k_prepB(const float* __restrict__ U1v, const float* __restrict__ U1g,
                                               const float* __restrict__ U1b, const float* __restrict__ U2v,
                                               const float* __restrict__ U2g, const float* __restrict__ U2b)
{
    __shared__ float red[8];
    const int w = blockIdx.x;            // 0..127
    const int t = threadIdx.x;
    const float* v = (w < 64) ? (U1v + (size_t)w * VD) : (U2v + (size_t)(w - 64) * VD);

    float x[8];
    float ss = 0.f;
    #pragma unroll
    for (int i = 0; i < 8; i++) { x[i] = v[t + i * 256]; ss = fmaf(x[i], x[i], ss); }
    #pragma unroll
    for (int o = 16; o > 0; o >>= 1) ss += __shfl_xor_sync(0xffffffffu, ss, o);
    if ((t & 31) == 0) red[t >> 5] = ss;
    __syncthreads();
    if (t == 0) {
        float tot = 0.f;
        #pragma unroll
        for (int i = 0; i < 8; i++) tot += red[i];
        float gg = (w < 64) ? U1g[w] : U2g[w - 64];
        float bb = (w < 64) ? U1b[w] : U2b[w - 64];
        g_scale[w] = gg / sqrtf(tot);
        g_bias[w]  = bb;
    }
    #pragma unroll
    for (int i = 0; i < 8; i++)
        g_Bh[w * VD + t + i * 256] = __float2half_rn(x[i]);
}

// ---------------- mma helpers ----------------
__device__ __forceinline__ void ldsm4(uint32_t* r, uint32_t a) {
    asm volatile("ldmatrix.sync.aligned.m8n8.x4.shared.b16 {%0,%1,%2,%3}, [%4];"
                 : "=r"(r[0]), "=r"(r[1]), "=r"(r[2]), "=r"(r[3]) : "r"(a));
}
__device__ __forceinline__ void mma16816(float* d, const uint32_t* a, const uint32_t* b) {
    asm volatile("mma.sync.aligned.m16n8k16.row.col.f32.f16.f16.f32 "
                 "{%0,%1,%2,%3},{%4,%5,%6,%7},{%8,%9},{%0,%1,%2,%3};"
                 : "+f"(d[0]), "+f"(d[1]), "+f"(d[2]), "+f"(d[3])
                 : "r"(a[0]), "r"(a[1]), "r"(a[2]), "r"(a[3]), "r"(b[0]), "r"(b[1]));
}
__device__ __forceinline__ void cp16(uint32_t dst, const void* src) {
    asm volatile("cp.async.ca.shared.global [%0], [%1], 16;" :: "r"(dst), "l"(src));
}
__device__ __forceinline__ unsigned h2bits(__half2 h) {
    return *reinterpret_cast<unsigned*>(&h);
}
// fp32x4 -> fp16x4 (round-to-nearest), packed
__device__ __forceinline__ uint2 packh(float4 av) {
    __half2 h01 = __float22half2_rn(make_float2(av.x, av.y));
    __half2 h23 = __float22half2_rn(make_float2(av.z, av.w));
    uint2 hu; hu.x = h2bits(h01); hu.y = h2bits(h23);
    return hu;
}

// ---------------- Kernel B: GEMM1 (single fp16 product, BM=64/BK=32) ----------------
// C[16384,128] = relu( (A[16384,2048] @ Wcat[128,2048]^T) * scale + bias )
// 256 CTAs, 8 warps as 2(M)x4(N): warp tile M32xN32. 64 stages.
// Per stage per warp: 16 HMMA vs 8 ldsm + 1 sync.
// A: fp32 LDG 2-stage reg lookahead -> fp16 -> smem (2 bufs).
// B: fp16 via cp.async, 4-slot ring, issue s+3, wait_group 2.
// Error: A*eB + B*eA ~ sqrt(2)*2^-12 relative (measured 3.3e-4 with eB alone).
__global__ __launch_bounds__(256, 2) void k_gemm1(const float* __restrict__ A)
{
    extern __shared__ char dsm[];
    const uint32_t uB0 = (uint32_t)__cvta_generic_to_shared(dsm);
    const uint32_t uAh = uB0;                  // 2 x ABUFA
    const uint32_t uBh = uB0 + 2 * ABUFA;      // 4 x BSLOT
    char* pAh = dsm;

    const int t = threadIdx.x, lane = t & 31, warp = t >> 5;
    const int wy = warp >> 2;           // 0..1  (M half, 32 rows)
    const int wx = warp & 3;            // 0..3  (N quarter, 32 cols)
    const int blockRow = blockIdx.x * 64;

    // ---- A loader role: row = t>>2 (0..63), 8 floats at (t&3)*8 ----
    const int arow = t >> 2, ak = (t & 3) * 8;
    const float* Ap = A + (size_t)(blockRow + arow) * VD + ak;
    const uint32_t aSt = (uint32_t)(arow * ROWB + ak * 2);    // byte offset in buffer

    // ---- B loader role: row = t>>1 (0..127), 32B seg at (t&1)*32 ----
    const int brow = t >> 1, sg = t & 1;
    const __half* Bp = g_Bh + (size_t)brow * VD + sg * 16;    // 16 halves = 32B
    const uint32_t bDst = (uint32_t)(brow * ROWB + sg * 32);

    float acc[2][4][4];
    #pragma unroll
    for (int mi = 0; mi < 2; mi++)
        #pragma unroll
        for (int nt = 0; nt < 4; nt++)
            #pragma unroll
            for (int j = 0; j < 4; j++) acc[mi][nt][j] = 0.f;

    // ---- prologue: B slots 0..2 ----
    #pragma unroll
    for (int sl = 0; sl < 3; sl++) {
        cp16(uBh + sl * BSLOT + bDst,      Bp + sl * BK2);
        cp16(uBh + sl * BSLOT + bDst + 16, Bp + sl * BK2 + 8);
        asm volatile("cp.async.commit_group;");
    }
    // A stage 0 -> buf 0
    {
        #pragma unroll
        for (int j = 0; j < 2; j++) {
            float4 v = *(const float4*)(Ap + j * 4);
            *(uint2*)(pAh + aSt + j * 8) = packh(v);
        }
    }
    // A stage 1 into regs
    float4 a_cur[2];
    #pragma unroll
    for (int j = 0; j < 2; j++) a_cur[j] = *(const float4*)(Ap + BK2 + j * 4);

    asm volatile("cp.async.wait_group 2;");   // slot 0 ready
    __syncthreads();

    // per-warp ldmatrix byte offsets
    const uint32_t aLdBase = (uint32_t)((wy * 32 + (lane & 15)) * AST2 + ((lane >> 4) << 3)) * 2;
    const uint32_t bLdBase = (uint32_t)((wx * 32 + (lane & 7) + ((lane >> 4) << 3)) * AST2
                                        + (((lane >> 3) & 1) << 3)) * 2;
    const uint32_t mStep = (uint32_t)(16 * AST2 * 2);  // 16 rows in bytes (1280)

    for (int s = 0; s < NS2; ++s) {
        const int sl = s & 3, slp = (s + 3) & 3, ab = s & 1;
        if (s + 3 < NS2) {
            cp16(uBh + slp * BSLOT + bDst,      Bp + (s + 3) * BK2);
            cp16(uBh + slp * BSLOT + bDst + 16, Bp + (s + 3) * BK2 + 8);
        }
        asm volatile("cp.async.commit_group;");

        // A LDG for stage s+2
        float4 a_next[2];
        if (s + 2 < NS2) {
            #pragma unroll
            for (int j = 0; j < 2; j++)
                a_next[j] = *(const float4*)(Ap + (s + 2) * BK2 + j * 4);
        }
        // STS stage s+1 into buf (s+1)&1  (that buffer's readers synced last iter)
        if (s + 1 < NS2) {
            const uint32_t boff = (uint32_t)(((s + 1) & 1) * ABUFA) + aSt;
            #pragma unroll
            for (int j = 0; j < 2; j++)
                *(uint2*)(pAh + boff + j * 8) = packh(a_cur[j]);
        }
        #pragma unroll
        for (int j = 0; j < 2; j++) a_cur[j] = a_next[j];

        // ---- compute stage s: 2 k-subtiles x (2 mi x 4 nt) ----
        #pragma unroll
        for (int ks = 0; ks < 2; ks++) {
            const uint32_t kOff = (uint32_t)(ks * 32);   // 16 halves = 32B
            uint32_t ah[2][4], bh[2][4];
            #pragma unroll
            for (int mi = 0; mi < 2; mi++)
                ldsm4(ah[mi], uAh + ab * ABUFA + aLdBase + mi * mStep + kOff);
            #pragma unroll
            for (int nj = 0; nj < 2; nj++)
                ldsm4(bh[nj], uBh + sl * BSLOT + bLdBase + nj * mStep + kOff);
            #pragma unroll
            for (int mi = 0; mi < 2; mi++)
                #pragma unroll
                for (int nt = 0; nt < 4; nt++)
                    mma16816(acc[mi][nt], ah[mi], &bh[nt >> 1][(nt & 1) * 2]);
        }

        asm volatile("cp.async.wait_group 2;");
        __syncthreads();
    }

    // ---- epilogue: scale + bias + relu -> g_LR ----
    #pragma unroll
    for (int mi = 0; mi < 2; mi++) {
        const int r0 = blockRow + wy * 32 + mi * 16 + (lane >> 2);
        #pragma unroll
        for (int nt = 0; nt < 4; nt++) {
            const int col = wx * 32 + nt * 8 + ((lane & 3) << 1);
            const float s0 = g_scale[col], s1 = g_scale[col + 1];
            const float b0 = g_bias[col],  b1 = g_bias[col + 1];
            float2 v;
            v.x = fmaxf(fmaf(acc[mi][nt][0], s0, b0), 0.f);
            v.y = fmaxf(fmaf(acc[mi][nt][1], s1, b1), 0.f);
            *(float2*)&g_LR[(size_t)r0 * 128 + col] = v;
            v.x = fmaxf(fmaf(acc[mi][nt][2], s0, b0), 0.f);
            v.y = fmaxf(fmaf(acc[mi][nt][3], s1, b1), 0.f);
            *(float2*)&g_LR[(size_t)(r0 + 8) * 128 + col] = v;
        }
    }
}

// ---------------- Kernel C1: per-row d + 4-way partial u ----------------
// grid (4, BB), 256 threads; 4 lanes per row.
__global__ __launch_bounds__(256) void k_corrA()
{
    __shared__ float d_s[64];
    __shared__ float upart[4][64];
    const int b = blockIdx.y, q = blockIdx.x, t = threadIdx.x;
    const int row = t >> 2, c = t & 3;
    const int gr = b * NN + q * 64 + row;
    const float* myrow = g_LR + (size_t)gr * 128;

    float dot = 0.f;
    #pragma unroll
    for (int j = 0; j < 4; j++) {
        float4 r = ((const float4*)myrow)[c + j * 4];
        float4 l = ((const float4*)myrow)[16 + c + j * 4];
        dot += r.x * l.x + r.y * l.y + r.z * l.z + r.w * l.w;
    }
    dot += __shfl_xor_sync(0xffffffffu, dot, 1);
    dot += __shfl_xor_sync(0xffffffffu, dot, 2);
    const float dv = rsqrtf(dot + 1e-6f);
    if (c == 0) { d_s[row] = dv; g_D[gr] = dv; }
    __syncthreads();

    const int k = t & 63, g = t >> 6;
    float part = 0.f;
    const float* lb = g_LR + (size_t)(b * NN + q * 64 + g * 16) * 128 + 64 + k;
    #pragma unroll
    for (int n = 0; n < 16; n++)
        part = fmaf(d_s[g * 16 + n], lb[(size_t)n * 128], part);
    upart[g][k] = part;
    __syncthreads();
    if (t < 64)
        g_U4[(b * 4 + q) * 64 + t] = upart[0][t] + upart[1][t] + upart[2][t] + upart[3][t];
}

// ---------------- Kernel D: s[m] (fused corrB) + feats partials ----------------
// grid (2, 4, BB): x = v-half, y = m-quarter q, z = batch.
__global__ __launch_bounds__(256) void k_featsS(const float* __restrict__ V)
{
    __shared__ float u_s[64];
    __shared__ float ss[64];
    const int b = blockIdx.z, q = blockIdx.y;
    const int t = threadIdx.x;

    if (t < 64)
        u_s[t] = g_U4[(b * 4 + 0) * 64 + t] + g_U4[(b * 4 + 1) * 64 + t]
               + g_U4[(b * 4 + 2) * 64 + t] + g_U4[(b * 4 + 3) * 64 + t];
    __syncthreads();

    {   // s for this block's 64 rows (4 lanes per row)
        const int row = t >> 2, c = t & 3;
        const int gr = b * NN + q * 64 + row;
        const float* myrow = g_LR + (size_t)gr * 128;
        float sm = 0.f;
        #pragma unroll
        for (int j = 0; j < 4; j++) {
            float4 r = ((const float4*)myrow)[c * 4 + j];
            sm += u_s[c * 16 + j * 4 + 0] * r.x + u_s[c * 16 + j * 4 + 1] * r.y
                + u_s[c * 16 + j * 4 + 2] * r.z + u_s[c * 16 + j * 4 + 3] * r.w;
        }
        sm += __shfl_xor_sync(0xffffffffu, sm, 1);
        sm += __shfl_xor_sync(0xffffffffu, sm, 2);
        if (c == 0)
            ss[row] = 1.f + (1.f / 256.f) - (g_D[gr] * (1.f / 256.f)) * sm;
    }
    __syncthreads();

    const int v0 = (blockIdx.x * 256 + t) * 4;
    const float* base = V + (size_t)b * NN * VD + (size_t)q * 64 * VD + v0;
    float4 acc = make_float4(0.f, 0.f, 0.f, 0.f);
    #pragma unroll 4
    for (int m = 0; m < 64; m++) {
        float4 val = *(const float4*)(base + (size_t)m * VD);
        float sv = ss[m];
        acc.x = fmaf(sv, val.x, acc.x);
        acc.y = fmaf(sv, val.y, acc.y);
        acc.z = fmaf(sv, val.z, acc.z);
        acc.w = fmaf(sv, val.w, acc.w);
    }
    *(float4*)(g_feats4 + (size_t)(q * BB + b) * VD + v0) = acc;
}

// ---------------- Kernel E: split-K GEMM  x = feats @ W^T  ->  partials g_P ----------------
__global__ __launch_bounds__(256) void k_gemm2(const float* __restrict__ W)
{
    __shared__ float sA[32][65];
    __shared__ float sB[32][65];
    const int t = threadIdx.x;
    const int tx = t & 15, ty = t >> 4;
    const int e0 = blockIdx.x * 64;
    const int k0 = blockIdx.y * 256;
    const int lrow = t >> 2, lk = (t & 3) * 8;
    float acc[4][4] = {};

    for (int stage = 0; stage < 8; ++stage) {
        const int kb = k0 + stage * 32;
        float4 a0 = make_float4(0,0,0,0), a1 = make_float4(0,0,0,0);
        #pragma unroll
        for (int p = 0; p < 4; p++) {
            float4 t0 = *(const float4*)(g_feats4 + (size_t)(p * BB + lrow) * VD + kb + lk);
            float4 t1 = *(const float4*)(g_feats4 + (size_t)(p * BB + lrow) * VD + kb + lk + 4);
            a0.x += t0.x; a0.y += t0.y; a0.z += t0.z; a0.w += t0.w;
            a1.x += t1.x; a1.y += t1.y; a1.z += t1.z; a1.w += t1.w;
        }
        float4 w0 = *(const float4*)(W + (size_t)(e0 + lrow) * VD + kb + lk);
        float4 w1 = *(const float4*)(W + (size_t)(e0 + lrow) * VD + kb + lk + 4);
        __syncthreads();
        sA[lk+0][lrow]=a0.x; sA[lk+1][lrow]=a0.y; sA[lk+2][lrow]=a0.z; sA[lk+3][lrow]=a0.w;
        sA[lk+4][lrow]=a1.x; sA[lk+5][lrow]=a1.y; sA[lk+6][lrow]=a1.z; sA[lk+7][lrow]=a1.w;
        sB[lk+0][lrow]=w0.x; sB[lk+1][lrow]=w0.y; sB[lk+2][lrow]=w0.z; sB[lk+3][lrow]=w0.w;
        sB[lk+4][lrow]=w1.x; sB[lk+5][lrow]=w1.y; sB[lk+6][lrow]=w1.z; sB[lk+7][lrow]=w1.w;
        __syncthreads();
        #pragma unroll
        for (int k = 0; k < 32; k++) {
            float av[4], bv[4];
            #pragma unroll
            for (int i = 0; i < 4; i++) av[i] = sA[k][ty * 4 + i];
            #pragma unroll
            for (int j = 0; j < 4; j++) bv[j] = sB[k][tx * 4 + j];
            #pragma unroll
            for (int i = 0; i < 4; i++)
                #pragma unroll
                for (int j = 0; j < 4; j++) acc[i][j] = fmaf(av[i], bv[j], acc[i][j]);
        }
    }
    #pragma unroll
    for (int i = 0; i < 4; i++)
        #pragma unroll
        for (int j = 0; j < 4; j++)
            g_P[(size_t)(blockIdx.y * 64 + ty * 4 + i) * EMB + e0 + tx * 4 + j] = acc[i][j];
}

// ---------------- Kernel F: reduce split-K + BatchNorm (single memory pass) ----------------
__global__ __launch_bounds__(256) void k_bn(const float* __restrict__ b_lin,
                                            const float* __restrict__ gamma,
                                            const float* __restrict__ beta,
                                            float* __restrict__ out)
{
    const int e = blockIdx.x * 256 + threadIdx.x;
    const float bias = b_lin[e];
    float x[BB];
    float sum = 0.f;
    #pragma unroll
    for (int b = 0; b < BB; b++) {
        float v = bias;
        #pragma unroll
        for (int s = 0; s < 8; s++) v += g_P[(size_t)(s * BB + b) * EMB + e];
        x[b] = v; sum += v;
    }
    const float mu = sum * (1.f / BB);
    float sq = 0.f;
    #pragma unroll
    for (int b = 0; b < BB; b++) { float d = x[b] - mu; sq = fmaf(d, d, sq); }
    const float inv = rsqrtf(sq * (1.f / BB) + 1e-5f);
    const float ga = gamma[e] * inv, be = beta[e];
    #pragma unroll
    for (int b = 0; b < BB; b++)
        out[b * EMB + e] = fmaf(ga, x[b] - mu, be);
}

// ---------------- launch ----------------
extern "C" void kernel_launch(void* const* d_in, const int* in_sizes, int n_in,
                              void* d_out, int out_size)
{
    const float* Vmat = (const float*)d_in[0];
    const float* U1v  = (const float*)d_in[1];
    const float* U1g  = (const float*)d_in[2];
    const float* U1b  = (const float*)d_in[3];
    const float* U2v  = (const float*)d_in[4];
    const float* U2g  = (const float*)d_in[5];
    const float* U2b  = (const float*)d_in[6];
    const float* Wl   = (const float*)d_in[7];
    const float* bl   = (const float*)d_in[8];
    const float* gam  = (const float*)d_in[9];
    const float* bet  = (const float*)d_in[10];
    float* out = (float*)d_out;

    cudaFuncSetAttribute(k_gemm1, cudaFuncAttributeMaxDynamicSharedMemorySize, G1_SMEM);

    k_prepB<<<128, 256>>>(U1v, U1g, U1b, U2v, U2g, U2b);
    k_gemm1<<<MTOT / 64, 256, G1_SMEM>>>(Vmat);
    k_corrA<<<dim3(4, BB), 256>>>();
    k_featsS<<<dim3(2, 4, BB), 256>>>(Vmat);
    k_gemm2<<<dim3(EMB / 64, 8), 256>>>(Wl);
    k_bn<<<EMB / 256, 256>>>(bl, gam, bet, out);
}